// round 8
// baseline (speedup 1.0000x reference)
#include <cuda_runtime.h>
#include <cstdint>

// weight_quantize_fn: out = alpha * SF * q_kept * sign, with group-of-16 term budget.
// R8: kernels are at their measured memory walls (read-only ~4.1 TB/s, R+W ~6.4 TB/s
//     effective). Attack the ~5-6us of inter-kernel overhead instead:
//     - reduceB+reduceC merged into one 1-CTA kernel
//     - PDL (programmatic stream serialization) on reduceBC and quant; quant issues
//       its input loads BEFORE griddepcontrol.wait to overlap launch + load latency.

#define AT 256                  // reduceA block
#define MAXP 65536              // max partials (CTAs of reduceA)
#define QT 256

__device__ float2 g_part[MAXP];      // per-CTA (sum, sumsq) fp32 partials
__device__ float  g_consts[4];       // [0]=1/(std*alpha), [1]=-mean/(std*alpha), [2]=SF*alpha

typedef unsigned long long u64;

// ---- PDL primitives ----
__device__ __forceinline__ void pdl_wait() {
    asm volatile("griddepcontrol.wait;" ::: "memory");
}
__device__ __forceinline__ void pdl_trigger() {
    asm volatile("griddepcontrol.launch_dependents;");
}

// ---- packed f32x2 helpers (Blackwell) ----
__device__ __forceinline__ u64 pk2(float lo, float hi) {
    u64 r; asm("mov.b64 %0, {%1, %2};" : "=l"(r) : "f"(lo), "f"(hi)); return r;
}
__device__ __forceinline__ void upk2(u64 v, float& lo, float& hi) {
    asm("mov.b64 {%0, %1}, %2;" : "=f"(lo), "=f"(hi) : "l"(v));
}
__device__ __forceinline__ u64 ffma2(u64 a, u64 b, u64 c) {
    u64 d; asm("fma.rn.f32x2 %0, %1, %2, %3;" : "=l"(d) : "l"(a), "l"(b), "l"(c)); return d;
}
__device__ __forceinline__ u64 fadd2(u64 a, u64 b) {
    u64 d; asm("add.rn.f32x2 %0, %1, %2;" : "=l"(d) : "l"(a), "l"(b)); return d;
}
__device__ __forceinline__ u64 fmul2(u64 a, u64 b) {
    u64 d; asm("mul.rn.f32x2 %0, %1, %2;" : "=l"(d) : "l"(a), "l"(b)); return d;
}
__device__ __forceinline__ void stcs4(float4* p, float4 v) {
    asm volatile("st.global.cs.v4.f32 [%0], {%1, %2, %3, %4};"
                 :: "l"(p), "f"(v.x), "f"(v.y), "f"(v.z), "f"(v.w) : "memory");
}

// ---- stage A: one-shot CTAs, 1 float4/thread, fp32 partial per CTA ----
__global__ void __launch_bounds__(AT) reduceA(const float4* __restrict__ x, int nvec) {
    int idx = blockIdx.x * AT + threadIdx.x;
    float s = 0.f, q = 0.f;
    if (idx < nvec) {
        float4 a = x[idx];
        s = (a.x + a.y) + (a.z + a.w);
        q = (a.x * a.x + a.y * a.y) + (a.z * a.z + a.w * a.w);
    }
#pragma unroll
    for (int o = 16; o > 0; o >>= 1) {
        s += __shfl_down_sync(0xffffffffu, s, o);
        q += __shfl_down_sync(0xffffffffu, q, o);
    }
    __shared__ float ssw[AT / 32], sqw[AT / 32];
    int wid = threadIdx.x >> 5, lane = threadIdx.x & 31;
    if (lane == 0) { ssw[wid] = s; sqw[wid] = q; }
    __syncthreads();
    if (threadIdx.x == 0) {
        float ts = 0.f, tq = 0.f;
#pragma unroll
        for (int i = 0; i < AT / 32; i++) { ts += ssw[i]; tq += sqw[i]; }
        g_part[blockIdx.x] = make_float2(ts, tq);
    }
    pdl_trigger();   // all CTAs signal; dependents get visibility of g_part
}

// ---- stage BC: single CTA folds partials -> mean/std -> constants ----
__global__ void __launch_bounds__(1024) reduceBC(const float* __restrict__ alpha_p,
                                                 int nparts, long long n) {
    __shared__ double ss[1024], sq[1024];
    pdl_wait();                              // g_part from reduceA must be visible
    double s = 0.0, q = 0.0;
    for (int i = threadIdx.x; i < nparts; i += 1024) {
        float2 p = g_part[i];
        s += (double)p.x;
        q += (double)p.y;
    }
    ss[threadIdx.x] = s; sq[threadIdx.x] = q;
    __syncthreads();
    for (int o = 512; o > 0; o >>= 1) {
        if (threadIdx.x < o) {
            ss[threadIdx.x] += ss[threadIdx.x + o];
            sq[threadIdx.x] += sq[threadIdx.x + o];
        }
        __syncthreads();
    }
    if (threadIdx.x == 0) {
        double N = (double)n;
        double mean = ss[0] / N;
        double var  = (sq[0] - N * mean * mean) / (N - 1.0);   // unbiased (ddof=1)
        double stdv = sqrt(var);
        double alpha = (double)(*alpha_p);
        double inv = 1.0 / (stdv * alpha);
        g_consts[0] = (float)inv;
        g_consts[1] = (float)(-mean * inv);
        g_consts[2] = (float)((double)(1.0f / 7.0f) * alpha);  // SF (fp32 1/7) * alpha
    }
    __syncthreads();
    pdl_trigger();   // after g_consts store: dependents see the constants
}

// ---- quantize: one float4 per thread; 4-lane clusters own one group of 16 ----
__global__ void __launch_bounds__(QT) quant(const float4* __restrict__ xv,
                                            float4* __restrict__ ov,
                                            const int* __restrict__ ntp, int nvec) {
    // Reverse block order: consume the L2-resident tail left by reduceA first.
    int rb = gridDim.x - 1 - blockIdx.x;
    int idx = rb * blockDim.x + threadIdx.x;
    if (idx >= nvec) { pdl_wait(); return; }

    // ---- pre-wait section: everything independent of the reduction ----
    float4 v = xv[idx];                           // input load in flight during primary tail
    int nts = __ldg(ntp);
    pdl_wait();                                   // now g_consts is visible

    float scale = g_consts[0], bias = g_consts[1], C = g_consts[2];
    const float MAGIC = 8388608.0f;               // 2^23: RN add == round-half-even to int
    u64 s2 = pk2(scale, scale);
    u64 b2 = pk2(bias, bias);
    u64 seven2  = pk2(7.0f, 7.0f);
    u64 magic2  = pk2(MAGIC, MAGIC);
    u64 nmagic2 = pk2(-MAGIC, -MAGIC);
    u64 C2 = pk2(C, C);

    float X[4] = {v.x, v.y, v.z, v.w};

    float t[4], f[4];
#pragma unroll
    for (int p = 0; p < 2; p++) {
        u64 t2 = ffma2(pk2(X[2 * p], X[2 * p + 1]), s2, b2);    // t = x*scale + bias
        upk2(t2, t[2 * p], t[2 * p + 1]);
        float al = fminf(fabsf(t[2 * p]), 1.0f);                // |clip(t)| — FMNMX with |src|
        float ah = fminf(fabsf(t[2 * p + 1]), 1.0f);
        u64 f2 = ffma2(pk2(al, ah), seven2, magic2);            // f = 2^23 + q (round-half-even)
        upk2(f2, f[2 * p], f[2 * p + 1]);
    }

    // Group sum of q over the 16 elements owned by this 4-lane cluster.
    int qs = __float_as_int(f[0]) + __float_as_int(f[1]) +
             __float_as_int(f[2]) + __float_as_int(f[3]);
    qs += __shfl_xor_sync(0xffffffffu, qs, 1);
    qs += __shfl_xor_sync(0xffffffffu, qs, 2);

    int budget = nts * 16;                        // num_terms * group_size

    float4 w;
    float* r = &w.x;
    // popc(q) <= (q+1)/2 for q in [0,7]  =>  sum(q) <= 2*budget-16 guarantees terms <= budget.
    if ((qs & 0xff) <= 2 * budget - 16) {
        // Fast path: every term kept -> qk == q.
#pragma unroll
        for (int p = 0; p < 2; p++) {
            u64 qf2 = fadd2(pk2(f[2 * p], f[2 * p + 1]), nmagic2);  // exact: qf = q as float
            u64 o2  = fmul2(qf2, C2);                               // |out| = q*SF*alpha
            float ol, oh; upk2(o2, ol, oh);
            r[2 * p]     = __int_as_float(__float_as_int(ol) | (__float_as_int(t[2 * p])     & 0x80000000));
            r[2 * p + 1] = __int_as_float(__float_as_int(oh) | (__float_as_int(t[2 * p + 1]) & 0x80000000));
        }
    } else {
        // Exact path (rare): stable-descending-sort semantics.
        int lane = threadIdx.x & 31;
        unsigned cmask = 0xFu << (lane & ~3);     // the 4 lanes of this cluster
        int pos = (lane & 3) * 4;                 // this lane's element offset in the group
        int m1 = 0, m2 = 0, m4 = 0;
#pragma unroll
        for (int k = 0; k < 4; k++) {
            int q = __float_as_int(f[k]) & 7;
            m1 |= (q & 1) << (pos + k);
            m2 |= ((q >> 1) & 1) << (pos + k);
            m4 |= ((q >> 2) & 1) << (pos + k);
        }
        m1 |= __shfl_xor_sync(cmask, m1, 1);  m1 |= __shfl_xor_sync(cmask, m1, 2);
        m2 |= __shfl_xor_sync(cmask, m2, 1);  m2 |= __shfl_xor_sync(cmask, m2, 2);
        m4 |= __shfl_xor_sync(cmask, m4, 1);  m4 |= __shfl_xor_sync(cmask, m4, 2);
        int c4 = min(__popc(m4), budget);
        int rem = budget - c4;
        int c2 = min(__popc(m2), rem); rem -= c2;
        int c1 = min(__popc(m1), rem);
        if (c1 < 0) c1 = 0;
#pragma unroll
        for (int k = 0; k < 4; k++) {
            int i16 = pos + k;
            int below = (1 << i16) - 1;
            int k4 = ((m4 >> i16) & 1) & ((__popc(m4 & below) < c4) ? 1 : 0);
            int k2 = ((m2 >> i16) & 1) & ((__popc(m2 & below) < c2) ? 1 : 0);
            int k1 = ((m1 >> i16) & 1) & ((__popc(m1 & below) < c1) ? 1 : 0);
            int kept = (k4 << 2) | (k2 << 1) | k1;
            float o = (float)kept * C;
            r[k] = __int_as_float(__float_as_int(o) | (__float_as_int(t[k]) & 0x80000000));
        }
    }

    stcs4(&ov[idx], w);                           // coalesced streaming store
}

extern "C" void kernel_launch(void* const* d_in, const int* in_sizes, int n_in,
                              void* d_out, int out_size) {
    const float* w     = (const float*)d_in[0];
    const float* alpha = (const float*)d_in[1];
    const int*   nt    = (const int*)d_in[2];
    int n = in_sizes[0];
    int nvec = n / 4;

    int na = (nvec + AT - 1) / AT;                // 32768 for 4096x8192
    if (na > MAXP) na = MAXP;

    reduceA<<<na, AT>>>((const float4*)w, nvec);

    // reduceBC with PDL: launches during reduceA's tail; waits for g_part visibility.
    {
        cudaLaunchAttribute attr[1];
        attr[0].id = cudaLaunchAttributeProgrammaticStreamSerialization;
        attr[0].val.programmaticStreamSerializationAllowed = 1;
        cudaLaunchConfig_t cfg = {};
        cfg.gridDim = dim3(1, 1, 1);
        cfg.blockDim = dim3(1024, 1, 1);
        cfg.attrs = attr;
        cfg.numAttrs = 1;
        cfg.stream = 0;
        cudaLaunchKernelEx(&cfg, reduceBC, alpha, na, (long long)n);
    }

    // quant with PDL: first wave launches during reduceBC, issues input LDGs pre-wait.
    {
        int qb = (nvec + QT - 1) / QT;
        cudaLaunchAttribute attr[1];
        attr[0].id = cudaLaunchAttributeProgrammaticStreamSerialization;
        attr[0].val.programmaticStreamSerializationAllowed = 1;
        cudaLaunchConfig_t cfg = {};
        cfg.gridDim = dim3(qb, 1, 1);
        cfg.blockDim = dim3(QT, 1, 1);
        cfg.attrs = attr;
        cfg.numAttrs = 1;
        cfg.stream = 0;
        cudaLaunchKernelEx(&cfg, quant, (const float4*)w, (float4*)d_out, nt, nvec);
    }
}

// round 9
// speedup vs baseline: 1.0110x; 1.0110x over previous
#include <cuda_runtime.h>
#include <cstdint>

// weight_quantize_fn: out = alpha * SF * q_kept * sign, with group-of-16 term budget.
// R8: kernels are at their measured memory walls (read-only ~4.1 TB/s, R+W ~6.4 TB/s
//     effective). Attack the ~5-6us of inter-kernel overhead instead:
//     - reduceB+reduceC merged into one 1-CTA kernel
//     - PDL (programmatic stream serialization) on reduceBC and quant; quant issues
//       its input loads BEFORE griddepcontrol.wait to overlap launch + load latency.

#define AT 256                  // reduceA block
#define MAXP 65536              // max partials (CTAs of reduceA)
#define QT 256

__device__ float2 g_part[MAXP];      // per-CTA (sum, sumsq) fp32 partials
__device__ float  g_consts[4];       // [0]=1/(std*alpha), [1]=-mean/(std*alpha), [2]=SF*alpha

typedef unsigned long long u64;

// ---- PDL primitives ----
__device__ __forceinline__ void pdl_wait() {
    asm volatile("griddepcontrol.wait;" ::: "memory");
}
__device__ __forceinline__ void pdl_trigger() {
    asm volatile("griddepcontrol.launch_dependents;");
}

// ---- packed f32x2 helpers (Blackwell) ----
__device__ __forceinline__ u64 pk2(float lo, float hi) {
    u64 r; asm("mov.b64 %0, {%1, %2};" : "=l"(r) : "f"(lo), "f"(hi)); return r;
}
__device__ __forceinline__ void upk2(u64 v, float& lo, float& hi) {
    asm("mov.b64 {%0, %1}, %2;" : "=f"(lo), "=f"(hi) : "l"(v));
}
__device__ __forceinline__ u64 ffma2(u64 a, u64 b, u64 c) {
    u64 d; asm("fma.rn.f32x2 %0, %1, %2, %3;" : "=l"(d) : "l"(a), "l"(b), "l"(c)); return d;
}
__device__ __forceinline__ u64 fadd2(u64 a, u64 b) {
    u64 d; asm("add.rn.f32x2 %0, %1, %2;" : "=l"(d) : "l"(a), "l"(b)); return d;
}
__device__ __forceinline__ u64 fmul2(u64 a, u64 b) {
    u64 d; asm("mul.rn.f32x2 %0, %1, %2;" : "=l"(d) : "l"(a), "l"(b)); return d;
}
__device__ __forceinline__ void stcs4(float4* p, float4 v) {
    asm volatile("st.global.cs.v4.f32 [%0], {%1, %2, %3, %4};"
                 :: "l"(p), "f"(v.x), "f"(v.y), "f"(v.z), "f"(v.w) : "memory");
}

// ---- stage A: one-shot CTAs, 1 float4/thread, fp32 partial per CTA ----
__global__ void __launch_bounds__(AT) reduceA(const float4* __restrict__ x, int nvec) {
    int idx = blockIdx.x * AT + threadIdx.x;
    float s = 0.f, q = 0.f;
    if (idx < nvec) {
        float4 a = x[idx];
        s = (a.x + a.y) + (a.z + a.w);
        q = (a.x * a.x + a.y * a.y) + (a.z * a.z + a.w * a.w);
    }
#pragma unroll
    for (int o = 16; o > 0; o >>= 1) {
        s += __shfl_down_sync(0xffffffffu, s, o);
        q += __shfl_down_sync(0xffffffffu, q, o);
    }
    __shared__ float ssw[AT / 32], sqw[AT / 32];
    int wid = threadIdx.x >> 5, lane = threadIdx.x & 31;
    if (lane == 0) { ssw[wid] = s; sqw[wid] = q; }
    __syncthreads();
    if (threadIdx.x == 0) {
        float ts = 0.f, tq = 0.f;
#pragma unroll
        for (int i = 0; i < AT / 32; i++) { ts += ssw[i]; tq += sqw[i]; }
        g_part[blockIdx.x] = make_float2(ts, tq);
    }
    pdl_trigger();   // all CTAs signal; dependents get visibility of g_part
}

// ---- stage BC: single CTA folds partials -> mean/std -> constants ----
__global__ void __launch_bounds__(1024) reduceBC(const float* __restrict__ alpha_p,
                                                 int nparts, long long n) {
    __shared__ double ss[1024], sq[1024];
    pdl_wait();                              // g_part from reduceA must be visible
    double s = 0.0, q = 0.0;
    for (int i = threadIdx.x; i < nparts; i += 1024) {
        float2 p = g_part[i];
        s += (double)p.x;
        q += (double)p.y;
    }
    ss[threadIdx.x] = s; sq[threadIdx.x] = q;
    __syncthreads();
    for (int o = 512; o > 0; o >>= 1) {
        if (threadIdx.x < o) {
            ss[threadIdx.x] += ss[threadIdx.x + o];
            sq[threadIdx.x] += sq[threadIdx.x + o];
        }
        __syncthreads();
    }
    if (threadIdx.x == 0) {
        double N = (double)n;
        double mean = ss[0] / N;
        double var  = (sq[0] - N * mean * mean) / (N - 1.0);   // unbiased (ddof=1)
        double stdv = sqrt(var);
        double alpha = (double)(*alpha_p);
        double inv = 1.0 / (stdv * alpha);
        g_consts[0] = (float)inv;
        g_consts[1] = (float)(-mean * inv);
        g_consts[2] = (float)((double)(1.0f / 7.0f) * alpha);  // SF (fp32 1/7) * alpha
    }
    __syncthreads();
    pdl_trigger();   // after g_consts store: dependents see the constants
}

// ---- quantize: one float4 per thread; 4-lane clusters own one group of 16 ----
__global__ void __launch_bounds__(QT) quant(const float4* __restrict__ xv,
                                            float4* __restrict__ ov,
                                            const int* __restrict__ ntp, int nvec) {
    // Reverse block order: consume the L2-resident tail left by reduceA first.
    int rb = gridDim.x - 1 - blockIdx.x;
    int idx = rb * blockDim.x + threadIdx.x;
    if (idx >= nvec) { pdl_wait(); return; }

    // ---- pre-wait section: everything independent of the reduction ----
    float4 v = xv[idx];                           // input load in flight during primary tail
    int nts = __ldg(ntp);
    pdl_wait();                                   // now g_consts is visible

    float scale = g_consts[0], bias = g_consts[1], C = g_consts[2];
    const float MAGIC = 8388608.0f;               // 2^23: RN add == round-half-even to int
    u64 s2 = pk2(scale, scale);
    u64 b2 = pk2(bias, bias);
    u64 seven2  = pk2(7.0f, 7.0f);
    u64 magic2  = pk2(MAGIC, MAGIC);
    u64 nmagic2 = pk2(-MAGIC, -MAGIC);
    u64 C2 = pk2(C, C);

    float X[4] = {v.x, v.y, v.z, v.w};

    float t[4], f[4];
#pragma unroll
    for (int p = 0; p < 2; p++) {
        u64 t2 = ffma2(pk2(X[2 * p], X[2 * p + 1]), s2, b2);    // t = x*scale + bias
        upk2(t2, t[2 * p], t[2 * p + 1]);
        float al = fminf(fabsf(t[2 * p]), 1.0f);                // |clip(t)| — FMNMX with |src|
        float ah = fminf(fabsf(t[2 * p + 1]), 1.0f);
        u64 f2 = ffma2(pk2(al, ah), seven2, magic2);            // f = 2^23 + q (round-half-even)
        upk2(f2, f[2 * p], f[2 * p + 1]);
    }

    // Group sum of q over the 16 elements owned by this 4-lane cluster.
    int qs = __float_as_int(f[0]) + __float_as_int(f[1]) +
             __float_as_int(f[2]) + __float_as_int(f[3]);
    qs += __shfl_xor_sync(0xffffffffu, qs, 1);
    qs += __shfl_xor_sync(0xffffffffu, qs, 2);

    int budget = nts * 16;                        // num_terms * group_size

    float4 w;
    float* r = &w.x;
    // popc(q) <= (q+1)/2 for q in [0,7]  =>  sum(q) <= 2*budget-16 guarantees terms <= budget.
    if ((qs & 0xff) <= 2 * budget - 16) {
        // Fast path: every term kept -> qk == q.
#pragma unroll
        for (int p = 0; p < 2; p++) {
            u64 qf2 = fadd2(pk2(f[2 * p], f[2 * p + 1]), nmagic2);  // exact: qf = q as float
            u64 o2  = fmul2(qf2, C2);                               // |out| = q*SF*alpha
            float ol, oh; upk2(o2, ol, oh);
            r[2 * p]     = __int_as_float(__float_as_int(ol) | (__float_as_int(t[2 * p])     & 0x80000000));
            r[2 * p + 1] = __int_as_float(__float_as_int(oh) | (__float_as_int(t[2 * p + 1]) & 0x80000000));
        }
    } else {
        // Exact path (rare): stable-descending-sort semantics.
        int lane = threadIdx.x & 31;
        unsigned cmask = 0xFu << (lane & ~3);     // the 4 lanes of this cluster
        int pos = (lane & 3) * 4;                 // this lane's element offset in the group
        int m1 = 0, m2 = 0, m4 = 0;
#pragma unroll
        for (int k = 0; k < 4; k++) {
            int q = __float_as_int(f[k]) & 7;
            m1 |= (q & 1) << (pos + k);
            m2 |= ((q >> 1) & 1) << (pos + k);
            m4 |= ((q >> 2) & 1) << (pos + k);
        }
        m1 |= __shfl_xor_sync(cmask, m1, 1);  m1 |= __shfl_xor_sync(cmask, m1, 2);
        m2 |= __shfl_xor_sync(cmask, m2, 1);  m2 |= __shfl_xor_sync(cmask, m2, 2);
        m4 |= __shfl_xor_sync(cmask, m4, 1);  m4 |= __shfl_xor_sync(cmask, m4, 2);
        int c4 = min(__popc(m4), budget);
        int rem = budget - c4;
        int c2 = min(__popc(m2), rem); rem -= c2;
        int c1 = min(__popc(m1), rem);
        if (c1 < 0) c1 = 0;
#pragma unroll
        for (int k = 0; k < 4; k++) {
            int i16 = pos + k;
            int below = (1 << i16) - 1;
            int k4 = ((m4 >> i16) & 1) & ((__popc(m4 & below) < c4) ? 1 : 0);
            int k2 = ((m2 >> i16) & 1) & ((__popc(m2 & below) < c2) ? 1 : 0);
            int k1 = ((m1 >> i16) & 1) & ((__popc(m1 & below) < c1) ? 1 : 0);
            int kept = (k4 << 2) | (k2 << 1) | k1;
            float o = (float)kept * C;
            r[k] = __int_as_float(__float_as_int(o) | (__float_as_int(t[k]) & 0x80000000));
        }
    }

    stcs4(&ov[idx], w);                           // coalesced streaming store
}

extern "C" void kernel_launch(void* const* d_in, const int* in_sizes, int n_in,
                              void* d_out, int out_size) {
    const float* w     = (const float*)d_in[0];
    const float* alpha = (const float*)d_in[1];
    const int*   nt    = (const int*)d_in[2];
    int n = in_sizes[0];
    int nvec = n / 4;

    int na = (nvec + AT - 1) / AT;                // 32768 for 4096x8192
    if (na > MAXP) na = MAXP;

    reduceA<<<na, AT>>>((const float4*)w, nvec);

    // reduceBC with PDL: launches during reduceA's tail; waits for g_part visibility.
    {
        cudaLaunchAttribute attr[1];
        attr[0].id = cudaLaunchAttributeProgrammaticStreamSerialization;
        attr[0].val.programmaticStreamSerializationAllowed = 1;
        cudaLaunchConfig_t cfg = {};
        cfg.gridDim = dim3(1, 1, 1);
        cfg.blockDim = dim3(1024, 1, 1);
        cfg.attrs = attr;
        cfg.numAttrs = 1;
        cfg.stream = 0;
        cudaLaunchKernelEx(&cfg, reduceBC, alpha, na, (long long)n);
    }

    // quant with PDL: first wave launches during reduceBC, issues input LDGs pre-wait.
    {
        int qb = (nvec + QT - 1) / QT;
        cudaLaunchAttribute attr[1];
        attr[0].id = cudaLaunchAttributeProgrammaticStreamSerialization;
        attr[0].val.programmaticStreamSerializationAllowed = 1;
        cudaLaunchConfig_t cfg = {};
        cfg.gridDim = dim3(qb, 1, 1);
        cfg.blockDim = dim3(QT, 1, 1);
        cfg.attrs = attr;
        cfg.numAttrs = 1;
        cfg.stream = 0;
        cudaLaunchKernelEx(&cfg, quant, (const float4*)w, (float4*)d_out, nt, nvec);
    }
}